// round 13
// baseline (speedup 1.0000x reference)
#include <cuda_runtime.h>
#include <cstdint>

#define DI __device__ __forceinline__

#if defined(__CUDA_ARCH__) && (defined(__CUDA_ARCH_FEAT_SM103_ALL) || defined(__CUDA_ARCH_FEAT_SM100_ALL))
#define USE_TCGEN05 1
#else
#define USE_TCGEN05 0
#endif

namespace {

constexpr int E_N  = 8;
constexpr int D_IN = 512;
constexpr int H_N  = 256;
constexpr int T_N  = 64;
constexpr int BM   = 128;        // batch rows per CTA
constexpr int NT   = 512;        // threads per CTA (16 warps)
constexpr int KC   = 32;         // fp32 elements per K chunk (128 B)
constexpr int NCH  = D_IN / KC;  // 16 chunks per expert
constexpr int NCTOT = NCH * E_N; // 128 chunks total
constexpr int B_MAX = 16384;
constexpr int A_TILE = 16384;    // bytes per A chunk tile (per CTA)
constexpr int W_TILE = 32768;    // bytes per full W chunk tile (16KB per rank-half)
constexpr int NB   = 5;          // pipeline stages

// ======== tcgen05 cg2 path smem layout (bytes) ========
constexpr int OFF_WT   = 0;        // Wt HALF tile (32 rows x 1024B, SW128) = 32KB
constexpr int OFF_GATE = 32768;    // gate [128][8] f32 = 4KB
constexpr int OFF_TM   = 36864;    // tmem ptr
constexpr int OFF_MBB  = 36872;    // 5 buffer-free mbarriers (8B each)
constexpr int OFF_MBF  = 36912;    // 5 buffer-full mbarriers
constexpr int OFF_MBT  = 36952;    // tower mbarrier
constexpr int OFF_BUF  = 37888;    // 1024-aligned stage region
constexpr int STAGE2   = 32768;    // A-half 16KB + W-half 16KB
// 5 stages end at 37888 + 163840 = 201728

// ======== fallback-path smem layout (bytes) ========
constexpr int FBUF_SZ = 55296;
constexpr int FB_A0   = 0;
constexpr int FB_W0   = 18432;
constexpr int FB_A1   = FBUF_SZ;
constexpr int FB_W1   = FBUF_SZ + 18432;
constexpr int FB_Y    = 0;
constexpr int FREGION = 133120;
constexpr int FB_WT   = FREGION;
constexpr int FB_WG   = FREGION + 66560;
constexpr int FB_GATE = FREGION + 82944;
constexpr int SMEM_SZ = FREGION + 87040;    // 220160 (covers both paths)

// cg2 idesc: dtype F32 (bit4), a=TF32 (2<<7), b=TF32 (2<<10), N/8 <<17, M/16 <<24
constexpr uint32_t IDESC_MAIN2 =
    (1u << 4) | (2u << 7) | (2u << 10) |
    ((uint32_t)(H_N / 8) << 17) | ((uint32_t)(256 / 16) << 24);
constexpr uint32_t IDESC_TWR2 =
    (1u << 4) | (2u << 7) | (2u << 10) |
    ((uint32_t)(T_N / 8) << 17) | ((uint32_t)(256 / 16) << 24);

// SW128 K-major smem descriptor: layout=2 (SW128), version=1, SBO=64, LBO=1
constexpr uint64_t DESC_BASE =
    (2ull << 61) | (1ull << 46) | (64ull << 32) | (1ull << 16);

constexpr int TMEM_D = 0;    // expert accumulator / Y operand, cols 0..255
constexpr int TMEM_Z = 256;  // tower accumulator cols 256..319

DI uint32_t smem_u32(const void* p) {
  uint32_t a;
  asm("{ .reg .u64 t; cvta.to.shared.u64 t, %1; cvt.u32.u64 %0, t; }"
      : "=r"(a) : "l"(p));
  return a;
}
DI uint32_t sw128(uint32_t x) { return x ^ ((x >> 3) & 0x70u); }
DI uint32_t f2tf(float f) {
  uint32_t r;
  asm("cvt.rna.tf32.f32 %0, %1;" : "=r"(r) : "f"(f));
  return r;
}
DI float sigmoidf_(float x) { return 1.0f / (1.0f + __expf(-x)); }

DI void cp16(uint32_t sdst, const void* gsrc) {
  asm volatile("cp.async.cg.shared.global [%0], [%1], 16;"
               ::"r"(sdst), "l"(gsrc) : "memory");
}
DI void cp_commit() { asm volatile("cp.async.commit_group;" ::: "memory"); }
template <int N>
DI void cp_wait() { asm volatile("cp.async.wait_group %0;" ::"n"(N) : "memory"); }

#if USE_TCGEN05
DI uint32_t elect1() {
  uint32_t p;
  asm volatile("{ .reg .pred p; elect.sync _|p, 0xFFFFFFFF; selp.b32 %0, 1, 0, p; }"
               : "=r"(p));
  return p;
}
DI uint32_t ctarank() {
  uint32_t r;
  asm("mov.u32 %0, %%cluster_ctarank;" : "=r"(r));
  return r;
}
DI void mbar_init(uint32_t a, uint32_t n) {
  asm volatile("mbarrier.init.shared.b64 [%0], %1;" ::"r"(a), "r"(n) : "memory");
}
DI void mbar_wait(uint32_t a, uint32_t par) {
  asm volatile(
      "{\n\t.reg .pred P;\n\t"
      "W_%=:\n\t"
      "mbarrier.try_wait.parity.acquire.cta.shared::cta.b64 P, [%0], %1, 0x989680;\n\t"
      "@P bra D_%=;\n\t"
      "bra W_%=;\n\t"
      "D_%=:\n\t}" ::"r"(a), "r"(par) : "memory");
}
DI void mbar_expect_tx(uint32_t a, uint32_t tx) {
  asm volatile("mbarrier.arrive.expect_tx.shared.b64 _, [%0], %1;"
               ::"r"(a), "r"(tx) : "memory");
}
// arrive on CTA-0's copy of a local mbarrier (cluster rank 0)
DI void arrive_peer0(uint32_t local_addr) {
  asm volatile(
      "{\n\t.reg .b32 r;\n\t"
      "mapa.shared::cluster.u32 r, %0, 0;\n\t"
      "mbarrier.arrive.shared::cluster.b64 _, [r];\n\t}"
      ::"r"(local_addr) : "memory");
}
DI void bulk_g2s(uint32_t sdst, const void* gsrc, uint32_t bytes, uint32_t mbar) {
  asm volatile(
      "cp.async.bulk.shared::cluster.global.mbarrier::complete_tx::bytes "
      "[%0], [%1], %2, [%3];"
      ::"r"(sdst), "l"(gsrc), "r"(bytes), "r"(mbar) : "memory");
}
DI void commit2_mc(uint32_t mb, uint16_t mask) {
  asm volatile(
      "tcgen05.commit.cta_group::2.mbarrier::arrive::one.shared::cluster"
      ".multicast::cluster.b64 [%0], %1;"
      ::"r"(mb), "h"(mask) : "memory");
}
DI void cluster_sync() {
  asm volatile("barrier.cluster.arrive.aligned;" ::: "memory");
  asm volatile("barrier.cluster.wait.aligned;" ::: "memory");
}
// cg2 SS form: A desc (halves across pair), B desc (N-halves across pair)
DI void mma_ss2(uint32_t d, uint64_t ad, uint64_t bd, uint32_t idesc, uint32_t en) {
  asm volatile(
      "{\n\t.reg .pred p;\n\t"
      "setp.ne.u32 p, %4, 0;\n\t"
      "tcgen05.mma.cta_group::2.kind::tf32 [%0], %1, %2, %3, "
      "{%5,%5,%5,%5,%5,%5,%5,%5}, p;\n\t}"
      ::"r"(d), "l"(ad), "l"(bd), "r"(idesc), "r"(en), "r"(0u) : "memory");
}
// cg2 TS form: A in TMEM (halves across pair), B desc
DI void mma_ts2(uint32_t d, uint32_t a_tm, uint64_t bd, uint32_t idesc, uint32_t en) {
  asm volatile(
      "{\n\t.reg .pred p;\n\t"
      "setp.ne.u32 p, %4, 0;\n\t"
      "tcgen05.mma.cta_group::2.kind::tf32 [%0], [%1], %2, %3, "
      "{%5,%5,%5,%5,%5,%5,%5,%5}, p;\n\t}"
      ::"r"(d), "r"(a_tm), "l"(bd), "r"(idesc), "r"(en), "r"(0u) : "memory");
}
#define LDTM_X32(R, A)                                                          \
  asm volatile(                                                                 \
      "tcgen05.ld.sync.aligned.32x32b.x32.b32 "                                 \
      "{%0,%1,%2,%3,%4,%5,%6,%7,%8,%9,%10,%11,%12,%13,%14,%15,"                 \
      "%16,%17,%18,%19,%20,%21,%22,%23,%24,%25,%26,%27,%28,%29,%30,%31}, "      \
      "[%32];"                                                                  \
      : "=r"((R)[0]), "=r"((R)[1]), "=r"((R)[2]), "=r"((R)[3]),                 \
        "=r"((R)[4]), "=r"((R)[5]), "=r"((R)[6]), "=r"((R)[7]),                 \
        "=r"((R)[8]), "=r"((R)[9]), "=r"((R)[10]), "=r"((R)[11]),               \
        "=r"((R)[12]), "=r"((R)[13]), "=r"((R)[14]), "=r"((R)[15]),             \
        "=r"((R)[16]), "=r"((R)[17]), "=r"((R)[18]), "=r"((R)[19]),             \
        "=r"((R)[20]), "=r"((R)[21]), "=r"((R)[22]), "=r"((R)[23]),             \
        "=r"((R)[24]), "=r"((R)[25]), "=r"((R)[26]), "=r"((R)[27]),             \
        "=r"((R)[28]), "=r"((R)[29]), "=r"((R)[30]), "=r"((R)[31])              \
      : "r"(A))
#define STTM_X32(A, R)                                                          \
  asm volatile(                                                                 \
      "tcgen05.st.sync.aligned.32x32b.x32.b32 [%0], "                           \
      "{%1,%2,%3,%4,%5,%6,%7,%8,%9,%10,%11,%12,%13,%14,%15,%16,"                \
      "%17,%18,%19,%20,%21,%22,%23,%24,%25,%26,%27,%28,%29,%30,%31,%32};"       \
      :: "r"(A),                                                                \
         "r"((R)[0]), "r"((R)[1]), "r"((R)[2]), "r"((R)[3]),                    \
         "r"((R)[4]), "r"((R)[5]), "r"((R)[6]), "r"((R)[7]),                    \
         "r"((R)[8]), "r"((R)[9]), "r"((R)[10]), "r"((R)[11]),                  \
         "r"((R)[12]), "r"((R)[13]), "r"((R)[14]), "r"((R)[15]),                \
         "r"((R)[16]), "r"((R)[17]), "r"((R)[18]), "r"((R)[19]),                \
         "r"((R)[20]), "r"((R)[21]), "r"((R)[22]), "r"((R)[23]),                \
         "r"((R)[24]), "r"((R)[25]), "r"((R)[26]), "r"((R)[27]),                \
         "r"((R)[28]), "r"((R)[29]), "r"((R)[30]), "r"((R)[31])                 \
      : "memory")
DI void wait_ld() { asm volatile("tcgen05.wait::ld.sync.aligned;" ::: "memory"); }
DI void wait_st() { asm volatile("tcgen05.wait::st.sync.aligned;" ::: "memory"); }
DI void fence_before() { asm volatile("tcgen05.fence::before_thread_sync;" ::: "memory"); }
DI void fence_after() { asm volatile("tcgen05.fence::after_thread_sync;" ::: "memory"); }
#else
// mma.sync m16n8k8 tf32: D += A*B (A row-major 16x8, B col-major 8x8)
DI void mma_s(float& d0, float& d1, float& d2, float& d3,
              uint32_t a0, uint32_t a1, uint32_t a2, uint32_t a3,
              uint32_t b0, uint32_t b1) {
  asm volatile(
      "mma.sync.aligned.m16n8k8.row.col.f32.tf32.tf32.f32 "
      "{%0,%1,%2,%3},{%4,%5,%6,%7},{%8,%9},{%0,%1,%2,%3};"
      : "+f"(d0), "+f"(d1), "+f"(d2), "+f"(d3)
      : "r"(a0), "r"(a1), "r"(a2), "r"(a3), "r"(b0), "r"(b1));
}
#endif

}  // namespace

// ---- device scratch: pre-rounded tf32 copies, chunk-contiguous, pre-swizzled:
// g_xv [rowblock][chunk][16KB], g_we [e][chunk][32KB (rows 0-127 | 128-255)]
__device__ float g_xv_tf[B_MAX * D_IN];             // 32 MB
__device__ float g_we_tf[E_N * H_N * D_IN];         // 4 MB

__global__ void __launch_bounds__(256)
preround_kernel(const float* __restrict__ xv, const float* __restrict__ We,
                int n_xv4) {
  const int n_we4 = (E_N * H_N * D_IN) / 4;
  int i = blockIdx.x * blockDim.x + threadIdx.x;
  if (i < n_xv4) {
    float4 v = ((const float4*)xv)[i];
    uint4 o;
    o.x = f2tf(v.x); o.y = f2tf(v.y); o.z = f2tf(v.z); o.w = f2tf(v.w);
    int row = i >> 7, k4 = i & 127;
    int rb = row >> 7, r = row & 127, c = k4 >> 3, j = k4 & 7;
    size_t off = ((size_t)(rb * NCH + c) << 14) + sw128((uint32_t)(r * 128 + j * 16));
    *(uint4*)((char*)g_xv_tf + off) = o;
  } else if (i < n_xv4 + n_we4) {
    int j0 = i - n_xv4;
    float4 v = ((const float4*)We)[j0];
    uint4 o;
    o.x = f2tf(v.x); o.y = f2tf(v.y); o.z = f2tf(v.z); o.w = f2tf(v.w);
    int e = j0 >> 15, rem = j0 & 32767;
    int h = rem >> 7, k4 = rem & 127, c = k4 >> 3, jj = k4 & 7;
    size_t off = ((size_t)(e * NCH + c) << 15) + sw128((uint32_t)(h * 128 + jj * 16));
    *(uint4*)((char*)g_we_tf + off) = o;
  }
}

extern __shared__ char smem[];

__global__ void __launch_bounds__(NT, 1)
mmoe_fused_kernel(const float* __restrict__ xv, const float* __restrict__ We,
                  const float* __restrict__ be, const float* __restrict__ Wg,
                  const float* __restrict__ bg, const float* __restrict__ Wt,
                  const float* __restrict__ bt, float* __restrict__ out) {
  const int tid = threadIdx.x;
  const int wid = tid >> 5;
  const int lid = tid & 31;
  const int row0 = blockIdx.x * BM;

#if USE_TCGEN05
  // =================== tcgen05 cg2 (sm_103a) path ===================
  const uint32_t sb = smem_u32(smem);
  const uint32_t rank = ctarank();
  const char* Axv = (const char*)g_xv_tf + ((size_t)blockIdx.x * NCH) * A_TILE;
  const char* Wwe = (const char*)g_we_tf;

  if (wid == 0) {
    asm volatile("tcgen05.alloc.cta_group::2.sync.aligned.shared::cta.b32 [%0], %1;"
                 ::"r"(sb + OFF_TM), "r"(512) : "memory");
  }
  if (tid == 0) {
#pragma unroll
    for (int i = 0; i < NB; ++i) {
      mbar_init(sb + OFF_MBB + i * 8, 1);                    // one mc-commit per use
      mbar_init(sb + OFF_MBF + i * 8, (rank == 0) ? 2 : 1);  // expect_tx (+peer arrive)
    }
    mbar_init(sb + OFF_MBT, 1);
  }
  // Wt HALF [rank*32 .. rank*32+31][256] -> tf32 blocked SW128 (4 atoms/k-block)
  for (int i4 = tid; i4 < (32 * H_N) / 4; i4 += NT) {
    int hh = i4 >> 6, kq = i4 & 63;
    float4 v = *(const float4*)(Wt + (size_t)(rank * 32 + hh) * H_N + kq * 4);
    uint32_t kb = (uint32_t)kq * 16;
    uint32_t off = ((kb >> 7) * 4 + (hh >> 3)) * 1024 + ((hh & 7) << 7) + (kb & 127);
    uint4 pk;
    pk.x = f2tf(v.x); pk.y = f2tf(v.y); pk.z = f2tf(v.z); pk.w = f2tf(v.w);
    *(uint4*)(smem + OFF_WT + sw128(off)) = pk;
  }
  __syncthreads();
  cluster_sync();   // peer mbarriers initialized before any cross-CTA signaling

  uint32_t tmem;
  asm volatile("ld.shared.b32 %0, [%1];" : "=r"(tmem) : "r"(sb + OFF_TM));

  const int sub = wid & 3;
  const int whalf = wid >> 2;
  const int m = sub * 32 + lid;
  float* gsm = (float*)(smem + OFF_GATE);

  // ---- producer prologue: chunks 0..3 (warp 0 of each rank, elected lane) ----
  if (wid == 0 && elect1()) {
#pragma unroll
    for (int pc = 0; pc < 4; ++pc) {
      const uint32_t mbf = sb + OFF_MBF + pc * 8;
      mbar_expect_tx(mbf, STAGE2);
      bulk_g2s(sb + OFF_BUF + pc * STAGE2, Axv + (size_t)pc * A_TILE, 16384, mbf);
      bulk_g2s(sb + OFF_BUF + pc * STAGE2 + 16384,
               Wwe + (size_t)pc * W_TILE + rank * 16384, 16384, mbf);
    }
  }
  if (wid == 0 && rank == 1) {
    if (elect1()) {      // forward chunk 0 completion to rank 0
      mbar_wait(sb + OFF_MBF + 0, 0);
      arrive_peer0(sb + OFF_MBF + 0);
    }
  }

  // ---- gate: warps 8-15, from raw fp32 xv, pre-mainloop ----
  if (wid >= 8) {
    const int t = tid - 256;
    const int row = t & 127;
    const int e0 = (t >> 7) * 4;
    float ga[4] = {0.f, 0.f, 0.f, 0.f};
    const float4* xr = (const float4*)(xv + (size_t)(row0 + row) * D_IN);
#pragma unroll 4
    for (int j4 = 0; j4 < 128; ++j4) {
      float4 x = xr[j4];
#pragma unroll
      for (int q = 0; q < 4; ++q) {
        float4 w = *(const float4*)(Wg + (e0 + q) * D_IN + j4 * 4);
        ga[q] += x.x * w.x + x.y * w.y + x.z * w.z + x.w * w.w;
      }
    }
#pragma unroll
    for (int q = 0; q < 4; ++q) gsm[row * 8 + e0 + q] = ga[q] + bg[e0 + q];
    asm volatile("bar.sync 1, 256;" ::: "memory");
    if (t < 128) {
      float l[E_N], mx = -1e30f;
#pragma unroll
      for (int i = 0; i < E_N; ++i) { l[i] = gsm[t * 8 + i]; mx = fmaxf(mx, l[i]); }
      float s = 0.f;
#pragma unroll
      for (int i = 0; i < E_N; ++i) { l[i] = __expf(l[i] - mx); s += l[i]; }
      float inv = 1.0f / s;
#pragma unroll
      for (int i = 0; i < E_N; ++i) gsm[t * 8 + i] = l[i] * inv;
    }
  }

  // =================== flat mainloop over 128 chunks ===================
  for (int ec = 0; ec < NCTOT; ++ec) {
    const int e = ec >> 4;
    const int c = ec & 15;
    const int b = ec % NB;

    // ---- producers: issue chunk ec+4; rank1 forwards completion of ec+1 ----
    if (wid == 0) {
      const int cn = ec + 4;
      if (cn < NCTOT && elect1()) {
        const int b2 = cn % NB, k = cn / NB;
        if (k >= 1) mbar_wait(sb + OFF_MBB + b2 * 8, (k - 1) & 1);
        const uint32_t mbf = sb + OFF_MBF + b2 * 8;
        mbar_expect_tx(mbf, STAGE2);
        bulk_g2s(sb + OFF_BUF + b2 * STAGE2, Axv + (size_t)(cn & 15) * A_TILE,
                 16384, mbf);
        bulk_g2s(sb + OFF_BUF + b2 * STAGE2 + 16384,
                 Wwe + (size_t)cn * W_TILE + rank * 16384, 16384, mbf);
      }
      if (rank == 1) {
        const int ca = ec + 1;
        if (ca < NCTOT && elect1()) {
          mbar_wait(sb + OFF_MBF + (ca % NB) * 8, (ca / NB) & 1);
          arrive_peer0(sb + OFF_MBF + (ca % NB) * 8);
        }
      }
    }

    // ---- consumer (rank 0 only): cg2 MMA for chunk ec ----
    if (rank == 0 && wid == 4) {
      if (elect1()) {
        if (c == 0 && e > 0) mbar_wait(sb + OFF_MBT, (e - 1) & 1);  // towers done
        mbar_wait(sb + OFF_MBF + b * 8, (ec / NB) & 1);
        const uint32_t base = OFF_BUF + b * STAGE2;
        uint64_t ad = DESC_BASE | (((sb + base) >> 4) & 0x3FFFu);
        uint64_t wd = DESC_BASE | (((sb + base + 16384) >> 4) & 0x3FFFu);
#pragma unroll
        for (int s = 0; s < 4; ++s)
          mma_ss2(tmem + TMEM_D, ad + 2 * s, wd + 2 * s, IDESC_MAIN2,
                  (uint32_t)((c > 0) || (s > 0)));
        commit2_mc(sb + OFF_MBB + b * 8, 0x3);   // buffer free on BOTH CTAs
      }
    }

    // ---- per-expert epilogue (all warps, both CTAs) ----
    if (c == 15) {
      mbar_wait(sb + OFF_MBB + b * 8, (ec / NB) & 1);  // chunk ec MMAs complete
      __syncthreads();   // also publishes gsm (gate) for e==0
      fence_after();
      // Y = gate * relu(D + be) in place in TMEM cols 0..255 (own 128 rows)
      {
        const float gv = gsm[m * 8 + e];
        const float* be_e = be + (size_t)e * H_N;
#pragma unroll
        for (int cb = 0; cb < 2; ++cb) {
          const int c0 = whalf * 64 + cb * 32;
          uint32_t r[32];
          LDTM_X32(r, tmem + TMEM_D + c0);
          wait_ld();
#pragma unroll
          for (int j = 0; j < 32; ++j)
            r[j] = f2tf(fmaxf(__uint_as_float(r[j]) + be_e[c0 + j], 0.f) * gv);
          STTM_X32(tmem + TMEM_D + c0, r);
          wait_st();
        }
      }
      fence_before();
      __syncthreads();
      cluster_sync();   // both CTAs' Y in TMEM before pair-wide tower MMA
      // tower: Z += Y @ Wt^T, cg2 TS (A = Y across pair, B = Wt halves)
      if (rank == 0 && wid == 4 && elect1()) {
        fence_after();
        const uint64_t wtd = DESC_BASE | (((sb + OFF_WT) >> 4) & 0x3FFFu);
#pragma unroll
        for (int s = 0; s < 32; ++s)
          mma_ts2(tmem + TMEM_Z, tmem + TMEM_D + s * 8,
                  wtd + (uint64_t)(s >> 2) * 256 + (s & 3) * 2, IDESC_TWR2,
                  (uint32_t)((e > 0) || (s > 0)));
        commit2_mc(sb + OFF_MBT, 0x3);
      }
    }
  }

  // ---- final: out = sigmoid(Z + bt) ----
  mbar_wait(sb + OFF_MBT, (E_N - 1) & 1);
  fence_after();
  if (wid < 8) {
    const int c0 = (wid >> 2) * 32;
    uint32_t r[32];
    LDTM_X32(r, tmem + TMEM_Z + c0);
    wait_ld();
    fence_before();
    float* orow = out + (size_t)(row0 + m) * T_N + c0;
#pragma unroll
    for (int jj = 0; jj < 8; ++jj) {
      float4 v;
      v.x = sigmoidf_(__uint_as_float(r[jj * 4 + 0]) + bt[c0 + jj * 4 + 0]);
      v.y = sigmoidf_(__uint_as_float(r[jj * 4 + 1]) + bt[c0 + jj * 4 + 1]);
      v.z = sigmoidf_(__uint_as_float(r[jj * 4 + 2]) + bt[c0 + jj * 4 + 2]);
      v.w = sigmoidf_(__uint_as_float(r[jj * 4 + 3]) + bt[c0 + jj * 4 + 3]);
      *(float4*)(orow + jj * 4) = v;
    }
  }
  __syncthreads();
  if (wid == 0) {
    asm volatile("tcgen05.relinquish_alloc_permit.cta_group::2.sync.aligned;");
    asm volatile("tcgen05.dealloc.cta_group::2.sync.aligned.b32 %0, %1;"
                 ::"r"(tmem), "r"(512));
  }
  cluster_sync();

#else
  // ================= mma.sync fallback path (compute_103) =================
  const uint32_t sb = smem_u32(smem);
  const float* Abase = xv + (size_t)row0 * D_IN;
  const int g   = lid >> 2;
  const int t4  = lid & 3;
  const int wm  = wid & 3;
  const int wn  = wid >> 2;
  float* gsm = (float*)(smem + FB_GATE);
  const uint32_t* Ysu = (const uint32_t*)(smem + FB_Y);
  uint32_t* Yw = (uint32_t*)(smem + FB_Y);
  const uint32_t* WTu = (const uint32_t*)(smem + FB_WT);

  for (int i4 = tid; i4 < (T_N * H_N) / 4; i4 += NT) {
    int t = i4 >> 6, kq = i4 & 63;
    float4 v = *(const float4*)(Wt + (size_t)t * H_N + kq * 4);
    uint32_t* dst = (uint32_t*)(smem + FB_WT) + t * 260 + kq * 4;
    dst[0] = f2tf(v.x); dst[1] = f2tf(v.y); dst[2] = f2tf(v.z); dst[3] = f2tf(v.w);
  }
  for (int i4 = tid; i4 < (E_N * D_IN) / 4; i4 += NT)
    *(float4*)(smem + FB_WG + i4 * 16) = *(const float4*)(Wg + i4 * 4);
  __syncthreads();

  const int grow = tid & 127;
  const int gelo = (tid >> 7) * 2;
  float gacc[2] = {0.f, 0.f};

  float z[2][2][4];
#pragma unroll
  for (int a = 0; a < 2; ++a)
#pragma unroll
    for (int b = 0; b < 2; ++b)
#pragma unroll
      for (int k = 0; k < 4; ++k) z[a][b][k] = 0.f;

  for (int e = 0; e < E_N; ++e) {
    const float* Wbase = We + (size_t)e * H_N * D_IN;
    float acc[2][8][4];
#pragma unroll
    for (int a = 0; a < 2; ++a)
#pragma unroll
      for (int b = 0; b < 8; ++b)
#pragma unroll
        for (int k = 0; k < 4; ++k) acc[a][b][k] = 0.f;

#pragma unroll
    for (int it = 0; it < 2; ++it) {
      int i = tid + it * NT, r = i >> 3, j4 = i & 7;
      cp16(sb + FB_A0 + r * 144 + j4 * 16, Abase + (size_t)r * D_IN + j4 * 4);
    }
#pragma unroll
    for (int it = 0; it < 4; ++it) {
      int i = tid + it * NT, r = i >> 3, j4 = i & 7;
      cp16(sb + FB_W0 + r * 144 + j4 * 16, Wbase + (size_t)r * D_IN + j4 * 4);
    }
    cp_commit();

    for (int c = 0; c < NCH; ++c) {
      if (c + 1 < NCH) {
        const uint32_t ab = ((c + 1) & 1) ? (sb + FB_A1) : (sb + FB_A0);
        const uint32_t wb = ((c + 1) & 1) ? (sb + FB_W1) : (sb + FB_W0);
        const int k0 = (c + 1) * KC;
#pragma unroll
        for (int it = 0; it < 2; ++it) {
          int i = tid + it * NT, r = i >> 3, j4 = i & 7;
          cp16(ab + r * 144 + j4 * 16, Abase + (size_t)r * D_IN + k0 + j4 * 4);
        }
#pragma unroll
        for (int it = 0; it < 4; ++it) {
          int i = tid + it * NT, r = i >> 3, j4 = i & 7;
          cp16(wb + r * 144 + j4 * 16, Wbase + (size_t)r * D_IN + k0 + j4 * 4);
        }
        cp_commit();
        cp_wait<1>();
      } else {
        cp_wait<0>();
      }
      __syncthreads();

      const float* Asf = (const float*)(smem + ((c & 1) ? FB_A1 : FB_A0));
      const float* Wsf = (const float*)(smem + ((c & 1) ? FB_W1 : FB_W0));

      if (e == 0) {
#pragma unroll
        for (int j4 = 0; j4 < 8; ++j4) {
          float4 x = *(const float4*)(Asf + grow * 36 + j4 * 4);
#pragma unroll
          for (int q = 0; q < 2; ++q) {
            const float* wrow = (const float*)(smem + FB_WG) +
                                (gelo + q) * D_IN + c * KC + j4 * 4;
            gacc[q] += x.x * wrow[0] + x.y * wrow[1] + x.z * wrow[2] + x.w * wrow[3];
          }
        }
      }

#pragma unroll
      for (int ks = 0; ks < 4; ++ks) {
        const int kk = ks * 8;
        uint32_t a[2][4];
#pragma unroll
        for (int mt = 0; mt < 2; ++mt) {
          const int r = wm * 32 + mt * 16;
          a[mt][0] = f2tf(Asf[(r + g) * 36 + kk + t4]);
          a[mt][1] = f2tf(Asf[(r + g + 8) * 36 + kk + t4]);
          a[mt][2] = f2tf(Asf[(r + g) * 36 + kk + t4 + 4]);
          a[mt][3] = f2tf(Asf[(r + g + 8) * 36 + kk + t4 + 4]);
        }
#pragma unroll
        for (int nt = 0; nt < 8; ++nt) {
          const int n = wn * 64 + nt * 8 + g;
          const uint32_t b0 = f2tf(Wsf[n * 36 + kk + t4]);
          const uint32_t b1 = f2tf(Wsf[n * 36 + kk + t4 + 4]);
#pragma unroll
          for (int mt = 0; mt < 2; ++mt)
            mma_s(acc[mt][nt][0], acc[mt][nt][1], acc[mt][nt][2], acc[mt][nt][3],
                  a[mt][0], a[mt][1], a[mt][2], a[mt][3], b0, b1);
        }
      }
      __syncthreads();
    }

    if (e == 0) {
#pragma unroll
      for (int q = 0; q < 2; ++q)
        gsm[grow * 8 + gelo + q] = gacc[q] + bg[gelo + q];
      __syncthreads();
      if (tid < BM) {
        float l[E_N], mx = -1e30f;
#pragma unroll
        for (int i = 0; i < E_N; ++i) { l[i] = gsm[tid * 8 + i]; mx = fmaxf(mx, l[i]); }
        float s = 0.f;
#pragma unroll
        for (int i = 0; i < E_N; ++i) { l[i] = __expf(l[i] - mx); s += l[i]; }
        float inv = 1.0f / s;
#pragma unroll
        for (int i = 0; i < E_N; ++i) gsm[tid * 8 + i] = l[i] * inv;
      }
      __syncthreads();
    }

    const float* be_e = be + (size_t)e * H_N;
#pragma unroll
    for (int mt = 0; mt < 2; ++mt) {
      const int ra = wm * 32 + mt * 16 + g;
      const int rb = ra + 8;
      const float gva = gsm[ra * 8 + e];
      const float gvb = gsm[rb * 8 + e];
#pragma unroll
      for (int nt = 0; nt < 8; ++nt) {
        const int col = wn * 64 + nt * 8 + 2 * t4;
        const float b0 = be_e[col], b1 = be_e[col + 1];
        uint2 pa, pb;
        pa.x = f2tf(fmaxf(acc[mt][nt][0] + b0, 0.f) * gva);
        pa.y = f2tf(fmaxf(acc[mt][nt][1] + b1, 0.f) * gva);
        pb.x = f2tf(fmaxf(acc[mt][nt][2] + b0, 0.f) * gvb);
        pb.y = f2tf(fmaxf(acc[mt][nt][3] + b1, 0.f) * gvb);
        *(uint2*)(Yw + ra * 260 + col) = pa;
        *(uint2*)(Yw + rb * 260 + col) = pb;
      }
    }
    __syncthreads();

#pragma unroll 4
    for (int ks = 0; ks < 32; ++ks) {
      const int kk = ks * 8;
      uint32_t ta[2][4];
#pragma unroll
      for (int mt = 0; mt < 2; ++mt) {
        const int r = wm * 32 + mt * 16;
        ta[mt][0] = Ysu[(r + g) * 260 + kk + t4];
        ta[mt][1] = Ysu[(r + g + 8) * 260 + kk + t4];
        ta[mt][2] = Ysu[(r + g) * 260 + kk + t4 + 4];
        ta[mt][3] = Ysu[(r + g + 8) * 260 + kk + t4 + 4];
      }
#pragma unroll
      for (int nt = 0; nt < 2; ++nt) {
        const int n = wn * 16 + nt * 8 + g;
        const uint32_t b0 = WTu[n * 260 + kk + t4];
        const uint32_t b1 = WTu[n * 260 + kk + t4 + 4];
#pragma unroll
        for (int mt = 0; mt < 2; ++mt)
          mma_s(z[mt][nt][0], z[mt][nt][1], z[mt][nt][2], z[mt][nt][3],
                ta[mt][0], ta[mt][1], ta[mt][2], ta[mt][3], b0, b1);
      }
    }
    __syncthreads();
  }

#pragma unroll
  for (int mt = 0; mt < 2; ++mt) {
    const int ra = wm * 32 + mt * 16 + g;
    const int rb = ra + 8;
#pragma unroll
    for (int nt = 0; nt < 2; ++nt) {
      const int col = wn * 16 + nt * 8 + 2 * t4;
      const float b0 = bt[col], b1 = bt[col + 1];
      float2 va, vb;
      va.x = sigmoidf_(z[mt][nt][0] + b0);
      va.y = sigmoidf_(z[mt][nt][1] + b1);
      vb.x = sigmoidf_(z[mt][nt][2] + b0);
      vb.y = sigmoidf_(z[mt][nt][3] + b1);
      *(float2*)(out + (size_t)(row0 + ra) * T_N + col) = va;
      *(float2*)(out + (size_t)(row0 + rb) * T_N + col) = vb;
    }
  }
#endif
}

extern "C" void kernel_launch(void* const* d_in, const int* in_sizes, int n_in,
                              void* d_out, int out_size) {
  const float* xv = (const float*)d_in[0];
  const float* We = (const float*)d_in[1];
  const float* be = (const float*)d_in[2];
  const float* Wg = (const float*)d_in[3];
  const float* bg = (const float*)d_in[4];
  const float* Wt = (const float*)d_in[5];
  const float* bt = (const float*)d_in[6];
  float* out = (float*)d_out;

  const int B = in_sizes[0] / D_IN;  // 16384
  const int grid = B / BM;           // 128

  static int attr_set = 0;
  if (!attr_set) {
    cudaFuncSetAttribute(mmoe_fused_kernel,
                         cudaFuncAttributeMaxDynamicSharedMemorySize, SMEM_SZ);
    cudaFuncSetAttribute(mmoe_fused_kernel,
                         cudaFuncAttributeNonPortableClusterSizeAllowed, 1);
    attr_set = 1;
  }

  const int n_xv4 = (B * D_IN) / 4;
  const int total4 = n_xv4 + (E_N * H_N * D_IN) / 4;
  preround_kernel<<<(total4 + 255) / 256, 256>>>(xv, We, n_xv4);

  cudaLaunchConfig_t cfg = {};
  cfg.gridDim = {(unsigned)grid, 1, 1};
  cfg.blockDim = {NT, 1, 1};
  cfg.dynamicSmemBytes = SMEM_SZ;
  cudaLaunchAttribute attrs[1];
  attrs[0].id = cudaLaunchAttributeClusterDimension;
  attrs[0].val.clusterDim = {2, 1, 1};
  cfg.attrs = attrs;
  cfg.numAttrs = 1;
  cudaLaunchKernelEx(&cfg, mmoe_fused_kernel, xv, We, be, Wg, bg, Wt, bt, out);
}

// round 15
// speedup vs baseline: 1.0381x; 1.0381x over previous
#include <cuda_runtime.h>
#include <cstdint>

#define DI __device__ __forceinline__

#if defined(__CUDA_ARCH__) && (defined(__CUDA_ARCH_FEAT_SM103_ALL) || defined(__CUDA_ARCH_FEAT_SM100_ALL))
#define USE_TCGEN05 1
#else
#define USE_TCGEN05 0
#endif

namespace {

constexpr int E_N  = 8;
constexpr int D_IN = 512;
constexpr int H_N  = 256;
constexpr int T_N  = 64;
constexpr int BM   = 128;        // batch rows per CTA
constexpr int NT   = 512;        // threads per CTA (16 warps)
constexpr int KC   = 32;         // fp32 elements per K chunk (128 B)
constexpr int NCH  = D_IN / KC;  // 16 chunks per expert
constexpr int NCTOT = NCH * E_N; // 128 chunks total
constexpr int B_MAX = 16384;
constexpr int A_TILE = 16384;    // bytes per A chunk tile (per CTA)
constexpr int W_TILE = 32768;    // bytes per full W chunk tile (16KB per rank-half)
constexpr int NB   = 5;          // pipeline stages

// ======== tcgen05 cg2 path smem layout (bytes) ========
constexpr int OFF_WT   = 0;        // Wt HALF tile (32 rows x 1024B, SW128) = 32KB
constexpr int OFF_GATE = 32768;    // gate [128][8] f32 = 4KB
constexpr int OFF_TM   = 36864;    // tmem ptr
constexpr int OFF_MBB  = 36872;    // 5 buffer-free mbarriers (8B each)
constexpr int OFF_MBF  = 36912;    // 5 buffer-full mbarriers
constexpr int OFF_MBT  = 36952;    // tower mbarrier (single phase)
constexpr int OFF_BUF  = 37888;    // 1024-aligned stage region
constexpr int STAGE2   = 32768;    // A-half 16KB + W-half 16KB
// 5 stages end at 37888 + 163840 = 201728

// ======== fallback-path smem layout (bytes) ========
constexpr int FBUF_SZ = 55296;
constexpr int FB_A0   = 0;
constexpr int FB_W0   = 18432;
constexpr int FB_A1   = FBUF_SZ;
constexpr int FB_W1   = FBUF_SZ + 18432;
constexpr int FB_Y    = 0;
constexpr int FREGION = 133120;
constexpr int FB_WT   = FREGION;
constexpr int FB_WG   = FREGION + 66560;
constexpr int FB_GATE = FREGION + 82944;
constexpr int SMEM_SZ = FREGION + 87040;    // 220160 (covers both paths)

// cg2 idesc: dtype F32 (bit4), a=TF32 (2<<7), b=TF32 (2<<10), N/8 <<17, M/16 <<24
constexpr uint32_t IDESC_MAIN2 =
    (1u << 4) | (2u << 7) | (2u << 10) |
    ((uint32_t)(H_N / 8) << 17) | ((uint32_t)(256 / 16) << 24);
constexpr uint32_t IDESC_TWR2 =
    (1u << 4) | (2u << 7) | (2u << 10) |
    ((uint32_t)(T_N / 8) << 17) | ((uint32_t)(256 / 16) << 24);

// SW128 K-major smem descriptor: layout=2 (SW128), version=1, SBO=64, LBO=1
constexpr uint64_t DESC_BASE =
    (2ull << 61) | (1ull << 46) | (64ull << 32) | (1ull << 16);

constexpr int TMEM_D = 0;    // expert accumulator / Y operand, cols 0..255
constexpr int TMEM_Z = 256;  // tower accumulator cols 256..319

DI uint32_t smem_u32(const void* p) {
  uint32_t a;
  asm("{ .reg .u64 t; cvta.to.shared.u64 t, %1; cvt.u32.u64 %0, t; }"
      : "=r"(a) : "l"(p));
  return a;
}
DI uint32_t sw128(uint32_t x) { return x ^ ((x >> 3) & 0x70u); }
DI uint32_t f2tf(float f) {
  uint32_t r;
  asm("cvt.rna.tf32.f32 %0, %1;" : "=r"(r) : "f"(f));
  return r;
}
DI float sigmoidf_(float x) { return 1.0f / (1.0f + __expf(-x)); }

DI void cp16(uint32_t sdst, const void* gsrc) {
  asm volatile("cp.async.cg.shared.global [%0], [%1], 16;"
               ::"r"(sdst), "l"(gsrc) : "memory");
}
DI void cp_commit() { asm volatile("cp.async.commit_group;" ::: "memory"); }
template <int N>
DI void cp_wait() { asm volatile("cp.async.wait_group %0;" ::"n"(N) : "memory"); }

#if USE_TCGEN05
DI uint32_t elect1() {
  uint32_t p;
  asm volatile("{ .reg .pred p; elect.sync _|p, 0xFFFFFFFF; selp.b32 %0, 1, 0, p; }"
               : "=r"(p));
  return p;
}
DI uint32_t ctarank() {
  uint32_t r;
  asm("mov.u32 %0, %%cluster_ctarank;" : "=r"(r));
  return r;
}
DI void mbar_init(uint32_t a, uint32_t n) {
  asm volatile("mbarrier.init.shared.b64 [%0], %1;" ::"r"(a), "r"(n) : "memory");
}
DI void mbar_wait(uint32_t a, uint32_t par) {
  asm volatile(
      "{\n\t.reg .pred P;\n\t"
      "W_%=:\n\t"
      "mbarrier.try_wait.parity.acquire.cta.shared::cta.b64 P, [%0], %1, 0x989680;\n\t"
      "@P bra D_%=;\n\t"
      "bra W_%=;\n\t"
      "D_%=:\n\t}" ::"r"(a), "r"(par) : "memory");
}
DI void mbar_expect_tx(uint32_t a, uint32_t tx) {
  asm volatile("mbarrier.arrive.expect_tx.shared.b64 _, [%0], %1;"
               ::"r"(a), "r"(tx) : "memory");
}
// arrive on CTA-0's copy of a local mbarrier (cluster rank 0)
DI void arrive_peer0(uint32_t local_addr) {
  asm volatile(
      "{\n\t.reg .b32 r;\n\t"
      "mapa.shared::cluster.u32 r, %0, 0;\n\t"
      "mbarrier.arrive.shared::cluster.b64 _, [r];\n\t}"
      ::"r"(local_addr) : "memory");
}
DI void bulk_g2s(uint32_t sdst, const void* gsrc, uint32_t bytes, uint32_t mbar) {
  asm volatile(
      "cp.async.bulk.shared::cluster.global.mbarrier::complete_tx::bytes "
      "[%0], [%1], %2, [%3];"
      ::"r"(sdst), "l"(gsrc), "r"(bytes), "r"(mbar) : "memory");
}
DI void commit2_mc(uint32_t mb, uint16_t mask) {
  asm volatile(
      "tcgen05.commit.cta_group::2.mbarrier::arrive::one.shared::cluster"
      ".multicast::cluster.b64 [%0], %1;"
      ::"r"(mb), "h"(mask) : "memory");
}
DI void cluster_sync() {
  asm volatile("barrier.cluster.arrive.aligned;" ::: "memory");
  asm volatile("barrier.cluster.wait.aligned;" ::: "memory");
}
// cg2 SS form: A desc (halves across pair), B desc (N-halves across pair)
DI void mma_ss2(uint32_t d, uint64_t ad, uint64_t bd, uint32_t idesc, uint32_t en) {
  asm volatile(
      "{\n\t.reg .pred p;\n\t"
      "setp.ne.u32 p, %4, 0;\n\t"
      "tcgen05.mma.cta_group::2.kind::tf32 [%0], %1, %2, %3, "
      "{%5,%5,%5,%5,%5,%5,%5,%5}, p;\n\t}"
      ::"r"(d), "l"(ad), "l"(bd), "r"(idesc), "r"(en), "r"(0u) : "memory");
}
// cg2 TS form: A in TMEM (halves across pair), B desc
DI void mma_ts2(uint32_t d, uint32_t a_tm, uint64_t bd, uint32_t idesc, uint32_t en) {
  asm volatile(
      "{\n\t.reg .pred p;\n\t"
      "setp.ne.u32 p, %4, 0;\n\t"
      "tcgen05.mma.cta_group::2.kind::tf32 [%0], [%1], %2, %3, "
      "{%5,%5,%5,%5,%5,%5,%5,%5}, p;\n\t}"
      ::"r"(d), "r"(a_tm), "l"(bd), "r"(idesc), "r"(en), "r"(0u) : "memory");
}
#define LDTM_X32(R, A)                                                          \
  asm volatile(                                                                 \
      "tcgen05.ld.sync.aligned.32x32b.x32.b32 "                                 \
      "{%0,%1,%2,%3,%4,%5,%6,%7,%8,%9,%10,%11,%12,%13,%14,%15,"                 \
      "%16,%17,%18,%19,%20,%21,%22,%23,%24,%25,%26,%27,%28,%29,%30,%31}, "      \
      "[%32];"                                                                  \
      : "=r"((R)[0]), "=r"((R)[1]), "=r"((R)[2]), "=r"((R)[3]),                 \
        "=r"((R)[4]), "=r"((R)[5]), "=r"((R)[6]), "=r"((R)[7]),                 \
        "=r"((R)[8]), "=r"((R)[9]), "=r"((R)[10]), "=r"((R)[11]),               \
        "=r"((R)[12]), "=r"((R)[13]), "=r"((R)[14]), "=r"((R)[15]),             \
        "=r"((R)[16]), "=r"((R)[17]), "=r"((R)[18]), "=r"((R)[19]),             \
        "=r"((R)[20]), "=r"((R)[21]), "=r"((R)[22]), "=r"((R)[23]),             \
        "=r"((R)[24]), "=r"((R)[25]), "=r"((R)[26]), "=r"((R)[27]),             \
        "=r"((R)[28]), "=r"((R)[29]), "=r"((R)[30]), "=r"((R)[31])              \
      : "r"(A))
#define STTM_X32(A, R)                                                          \
  asm volatile(                                                                 \
      "tcgen05.st.sync.aligned.32x32b.x32.b32 [%0], "                           \
      "{%1,%2,%3,%4,%5,%6,%7,%8,%9,%10,%11,%12,%13,%14,%15,%16,"                \
      "%17,%18,%19,%20,%21,%22,%23,%24,%25,%26,%27,%28,%29,%30,%31,%32};"       \
      :: "r"(A),                                                                \
         "r"((R)[0]), "r"((R)[1]), "r"((R)[2]), "r"((R)[3]),                    \
         "r"((R)[4]), "r"((R)[5]), "r"((R)[6]), "r"((R)[7]),                    \
         "r"((R)[8]), "r"((R)[9]), "r"((R)[10]), "r"((R)[11]),                  \
         "r"((R)[12]), "r"((R)[13]), "r"((R)[14]), "r"((R)[15]),                \
         "r"((R)[16]), "r"((R)[17]), "r"((R)[18]), "r"((R)[19]),                \
         "r"((R)[20]), "r"((R)[21]), "r"((R)[22]), "r"((R)[23]),                \
         "r"((R)[24]), "r"((R)[25]), "r"((R)[26]), "r"((R)[27]),                \
         "r"((R)[28]), "r"((R)[29]), "r"((R)[30]), "r"((R)[31])                 \
      : "memory")
DI void wait_ld() { asm volatile("tcgen05.wait::ld.sync.aligned;" ::: "memory"); }
DI void wait_st() { asm volatile("tcgen05.wait::st.sync.aligned;" ::: "memory"); }
DI void fence_before() { asm volatile("tcgen05.fence::before_thread_sync;" ::: "memory"); }
DI void fence_after() { asm volatile("tcgen05.fence::after_thread_sync;" ::: "memory"); }
#else
// mma.sync m16n8k8 tf32: D += A*B (A row-major 16x8, B col-major 8x8)
DI void mma_s(float& d0, float& d1, float& d2, float& d3,
              uint32_t a0, uint32_t a1, uint32_t a2, uint32_t a3,
              uint32_t b0, uint32_t b1) {
  asm volatile(
      "mma.sync.aligned.m16n8k8.row.col.f32.tf32.tf32.f32 "
      "{%0,%1,%2,%3},{%4,%5,%6,%7},{%8,%9},{%0,%1,%2,%3};"
      : "+f"(d0), "+f"(d1), "+f"(d2), "+f"(d3)
      : "r"(a0), "r"(a1), "r"(a2), "r"(a3), "r"(b0), "r"(b1));
}
#endif

}  // namespace

// ---- device scratch: pre-rounded tf32 copies, chunk-contiguous, pre-swizzled:
// g_xv [rowblock][chunk][16KB], g_we [e][chunk][32KB (rows 0-127 | 128-255)]
__device__ float g_xv_tf[B_MAX * D_IN];             // 32 MB
__device__ float g_we_tf[E_N * H_N * D_IN];         // 4 MB

__global__ void __launch_bounds__(256)
preround_kernel(const float* __restrict__ xv, const float* __restrict__ We,
                int n_xv4) {
  const int n_we4 = (E_N * H_N * D_IN) / 4;
  int i = blockIdx.x * blockDim.x + threadIdx.x;
  if (i < n_xv4) {
    float4 v = ((const float4*)xv)[i];
    uint4 o;
    o.x = f2tf(v.x); o.y = f2tf(v.y); o.z = f2tf(v.z); o.w = f2tf(v.w);
    int row = i >> 7, k4 = i & 127;
    int rb = row >> 7, r = row & 127, c = k4 >> 3, j = k4 & 7;
    size_t off = ((size_t)(rb * NCH + c) << 14) + sw128((uint32_t)(r * 128 + j * 16));
    *(uint4*)((char*)g_xv_tf + off) = o;
  } else if (i < n_xv4 + n_we4) {
    int j0 = i - n_xv4;
    float4 v = ((const float4*)We)[j0];
    uint4 o;
    o.x = f2tf(v.x); o.y = f2tf(v.y); o.z = f2tf(v.z); o.w = f2tf(v.w);
    int e = j0 >> 15, rem = j0 & 32767;
    int h = rem >> 7, k4 = rem & 127, c = k4 >> 3, jj = k4 & 7;
    size_t off = ((size_t)(e * NCH + c) << 15) + sw128((uint32_t)(h * 128 + jj * 16));
    *(uint4*)((char*)g_we_tf + off) = o;
  }
}

extern __shared__ char smem[];

__global__ void __launch_bounds__(NT, 1)
mmoe_fused_kernel(const float* __restrict__ xv, const float* __restrict__ We,
                  const float* __restrict__ be, const float* __restrict__ Wg,
                  const float* __restrict__ bg, const float* __restrict__ Wt,
                  const float* __restrict__ bt, float* __restrict__ out) {
  const int tid = threadIdx.x;
  const int wid = tid >> 5;
  const int lid = tid & 31;
  const int row0 = blockIdx.x * BM;

#if USE_TCGEN05
  // =================== tcgen05 cg2 (sm_103a) path ===================
  const uint32_t sb = smem_u32(smem);
  const uint32_t rank = ctarank();
  const char* Axv = (const char*)g_xv_tf + ((size_t)blockIdx.x * NCH) * A_TILE;
  const char* Wwe = (const char*)g_we_tf;

  if (wid == 0) {
    asm volatile("tcgen05.alloc.cta_group::2.sync.aligned.shared::cta.b32 [%0], %1;"
                 ::"r"(sb + OFF_TM), "r"(512) : "memory");
  }
  if (tid == 0) {
#pragma unroll
    for (int i = 0; i < NB; ++i) {
      mbar_init(sb + OFF_MBB + i * 8, 1);                    // one mc-commit per use
      mbar_init(sb + OFF_MBF + i * 8, (rank == 0) ? 2 : 1);  // expect_tx (+peer arrive)
    }
    mbar_init(sb + OFF_MBT, 1);
  }
  // Wt HALF [rank*32 .. rank*32+31][256] -> tf32 blocked SW128 (4 atoms/k-block)
  for (int i4 = tid; i4 < (32 * H_N) / 4; i4 += NT) {
    int hh = i4 >> 6, kq = i4 & 63;
    float4 v = *(const float4*)(Wt + (size_t)(rank * 32 + hh) * H_N + kq * 4);
    uint32_t kb = (uint32_t)kq * 16;
    uint32_t off = ((kb >> 7) * 4 + (hh >> 3)) * 1024 + ((hh & 7) << 7) + (kb & 127);
    uint4 pk;
    pk.x = f2tf(v.x); pk.y = f2tf(v.y); pk.z = f2tf(v.z); pk.w = f2tf(v.w);
    *(uint4*)(smem + OFF_WT + sw128(off)) = pk;
  }
  __syncthreads();
  cluster_sync();   // peer mbarriers initialized before any cross-CTA signaling

  uint32_t tmem;
  asm volatile("ld.shared.b32 %0, [%1];" : "=r"(tmem) : "r"(sb + OFF_TM));

  const int sub = wid & 3;
  const int whalf = wid >> 2;
  const int m = sub * 32 + lid;
  float* gsm = (float*)(smem + OFF_GATE);

  // ---- producer prologue: chunks 0..3 (warp 0 of each rank, elected lane) ----
  if (wid == 0 && elect1()) {
#pragma unroll
    for (int pc = 0; pc < 4; ++pc) {
      const uint32_t mbf = sb + OFF_MBF + pc * 8;
      mbar_expect_tx(mbf, STAGE2);
      bulk_g2s(sb + OFF_BUF + pc * STAGE2, Axv + (size_t)pc * A_TILE, 16384, mbf);
      bulk_g2s(sb + OFF_BUF + pc * STAGE2 + 16384,
               Wwe + (size_t)pc * W_TILE + rank * 16384, 16384, mbf);
    }
  }
  if (wid == 0 && rank == 1) {
    if (elect1()) {      // forward chunks 0 and 1 completion to rank 0
#pragma unroll
      for (int pc = 0; pc < 2; ++pc) {
        mbar_wait(sb + OFF_MBF + pc * 8, 0);
        arrive_peer0(sb + OFF_MBF + pc * 8);
      }
    }
  }

  // ---- gate: warps 8-15, from raw fp32 xv, pre-mainloop ----
  if (wid >= 8) {
    const int t = tid - 256;
    const int row = t & 127;
    const int e0 = (t >> 7) * 4;
    float ga[4] = {0.f, 0.f, 0.f, 0.f};
    const float4* xr = (const float4*)(xv + (size_t)(row0 + row) * D_IN);
#pragma unroll 4
    for (int j4 = 0; j4 < 128; ++j4) {
      float4 x = xr[j4];
#pragma unroll
      for (int q = 0; q < 4; ++q) {
        float4 w = *(const float4*)(Wg + (e0 + q) * D_IN + j4 * 4);
        ga[q] += x.x * w.x + x.y * w.y + x.z * w.z + x.w * w.w;
      }
    }
#pragma unroll
    for (int q = 0; q < 4; ++q) gsm[row * 8 + e0 + q] = ga[q] + bg[e0 + q];
    asm volatile("bar.sync 1, 256;" ::: "memory");
    if (t < 128) {
      float l[E_N], mx = -1e30f;
#pragma unroll
      for (int i = 0; i < E_N; ++i) { l[i] = gsm[t * 8 + i]; mx = fmaxf(mx, l[i]); }
      float s = 0.f;
#pragma unroll
      for (int i = 0; i < E_N; ++i) { l[i] = __expf(l[i] - mx); s += l[i]; }
      float inv = 1.0f / s;
#pragma unroll
      for (int i = 0; i < E_N; ++i) gsm[t * 8 + i] = l[i] * inv;
    }
  }

  // =================== flat mainloop over 128 chunks ===================
  for (int ec = 0; ec < NCTOT; ++ec) {
    const int e = ec >> 4;
    const int c = ec & 15;
    const int b = ec % NB;

    // ---- producers: issue chunk ec+4; rank1 forwards completion of ec+2 ----
    if (wid == 0) {
      const int cn = ec + 4;
      if (cn < NCTOT && elect1()) {
        const int b2 = cn % NB, k = cn / NB;
        if (k >= 1) mbar_wait(sb + OFF_MBB + b2 * 8, (k - 1) & 1);
        const uint32_t mbf = sb + OFF_MBF + b2 * 8;
        mbar_expect_tx(mbf, STAGE2);
        bulk_g2s(sb + OFF_BUF + b2 * STAGE2, Axv + (size_t)(cn & 15) * A_TILE,
                 16384, mbf);
        bulk_g2s(sb + OFF_BUF + b2 * STAGE2 + 16384,
                 Wwe + (size_t)cn * W_TILE + rank * 16384, 16384, mbf);
      }
      if (rank == 1) {
        const int ca = ec + 2;
        if (ca < NCTOT && elect1()) {
          mbar_wait(sb + OFF_MBF + (ca % NB) * 8, (ca / NB) & 1);
          arrive_peer0(sb + OFF_MBF + (ca % NB) * 8);
        }
      }
    }

    // ---- consumer (rank 0 only): cg2 MMA for chunk ec ----
    // No tower wait: tcgen05 ops from this thread dispatch in order, so the
    // previous expert's tower (reads TMEM_D) precedes this overwrite.
    if (rank == 0 && wid == 4) {
      if (elect1()) {
        mbar_wait(sb + OFF_MBF + b * 8, (ec / NB) & 1);
        const uint32_t base = OFF_BUF + b * STAGE2;
        uint64_t ad = DESC_BASE | (((sb + base) >> 4) & 0x3FFFu);
        uint64_t wd = DESC_BASE | (((sb + base + 16384) >> 4) & 0x3FFFu);
#pragma unroll
        for (int s = 0; s < 4; ++s)
          mma_ss2(tmem + TMEM_D, ad + 2 * s, wd + 2 * s, IDESC_MAIN2,
                  (uint32_t)((c > 0) || (s > 0)));
        commit2_mc(sb + OFF_MBB + b * 8, 0x3);   // buffer free on BOTH CTAs
      }
    }

    // ---- per-expert epilogue (all warps, both CTAs) ----
    if (c == 15) {
      mbar_wait(sb + OFF_MBB + b * 8, (ec / NB) & 1);  // chunk ec MMAs complete
      __syncthreads();   // also publishes gsm (gate) for e==0
      fence_after();
      // Y = gate * relu(D + be) in place in TMEM cols 0..255 (own 128 rows)
      {
        const float gv = gsm[m * 8 + e];
        const float* be_e = be + (size_t)e * H_N;
#pragma unroll
        for (int cb = 0; cb < 2; ++cb) {
          const int c0 = whalf * 64 + cb * 32;
          uint32_t r[32];
          LDTM_X32(r, tmem + TMEM_D + c0);
          wait_ld();
#pragma unroll
          for (int j = 0; j < 32; ++j)
            r[j] = f2tf(fmaxf(__uint_as_float(r[j]) + be_e[c0 + j], 0.f) * gv);
          STTM_X32(tmem + TMEM_D + c0, r);
          wait_st();
        }
      }
      fence_before();
      cluster_sync();   // both CTAs' Y in TMEM before pair-wide tower MMA
      // tower: Z += Y @ Wt^T, cg2 TS (A = Y across pair, B = Wt halves)
      if (rank == 0 && wid == 4 && elect1()) {
        fence_after();
        const uint64_t wtd = DESC_BASE | (((sb + OFF_WT) >> 4) & 0x3FFFu);
#pragma unroll
        for (int s = 0; s < 32; ++s)
          mma_ts2(tmem + TMEM_Z, tmem + TMEM_D + s * 8,
                  wtd + (uint64_t)(s >> 2) * 256 + (s & 3) * 2, IDESC_TWR2,
                  (uint32_t)((e > 0) || (s > 0)));
        if (e == E_N - 1) commit2_mc(sb + OFF_MBT, 0x3);  // single final commit
      }
    }
  }

  // ---- final: out = sigmoid(Z + bt) ----
  mbar_wait(sb + OFF_MBT, 0);
  fence_after();
  if (wid < 8) {
    const int c0 = (wid >> 2) * 32;
    uint32_t r[32];
    LDTM_X32(r, tmem + TMEM_Z + c0);
    wait_ld();
    fence_before();
    float* orow = out + (size_t)(row0 + m) * T_N + c0;
#pragma unroll
    for (int jj = 0; jj < 8; ++jj) {
      float4 v;
      v.x = sigmoidf_(__uint_as_float(r[jj * 4 + 0]) + bt[c0 + jj * 4 + 0]);
      v.y = sigmoidf_(__uint_as_float(r[jj * 4 + 1]) + bt[c0 + jj * 4 + 1]);
      v.z = sigmoidf_(__uint_as_float(r[jj * 4 + 2]) + bt[c0 + jj * 4 + 2]);
      v.w = sigmoidf_(__uint_as_float(r[jj * 4 + 3]) + bt[c0 + jj * 4 + 3]);
      *(float4*)(orow + jj * 4) = v;
    }
  }
  __syncthreads();
  if (wid == 0) {
    asm volatile("tcgen05.relinquish_alloc_permit.cta_group::2.sync.aligned;");
    asm volatile("tcgen05.dealloc.cta_group::2.sync.aligned.b32 %0, %1;"
                 ::"r"(tmem), "r"(512));
  }
  cluster_sync();

#else
  // ================= mma.sync fallback path (compute_103) =================
  const uint32_t sb = smem_u32(smem);
  const float* Abase = xv + (size_t)row0 * D_IN;
  const int g   = lid >> 2;
  const int t4  = lid & 3;
  const int wm  = wid & 3;
  const int wn  = wid >> 2;
  float* gsm = (float*)(smem + FB_GATE);
  const uint32_t* Ysu = (const uint32_t*)(smem + FB_Y);
  uint32_t* Yw = (uint32_t*)(smem + FB_Y);
  const uint32_t* WTu = (const uint32_t*)(smem + FB_WT);

  for (int i4 = tid; i4 < (T_N * H_N) / 4; i4 += NT) {
    int t = i4 >> 6, kq = i4 & 63;
    float4 v = *(const float4*)(Wt + (size_t)t * H_N + kq * 4);
    uint32_t* dst = (uint32_t*)(smem + FB_WT) + t * 260 + kq * 4;
    dst[0] = f2tf(v.x); dst[1] = f2tf(v.y); dst[2] = f2tf(v.z); dst[3] = f2tf(v.w);
  }
  for (int i4 = tid; i4 < (E_N * D_IN) / 4; i4 += NT)
    *(float4*)(smem + FB_WG + i4 * 16) = *(const float4*)(Wg + i4 * 4);
  __syncthreads();

  const int grow = tid & 127;
  const int gelo = (tid >> 7) * 2;
  float gacc[2] = {0.f, 0.f};

  float z[2][2][4];
#pragma unroll
  for (int a = 0; a < 2; ++a)
#pragma unroll
    for (int b = 0; b < 2; ++b)
#pragma unroll
      for (int k = 0; k < 4; ++k) z[a][b][k] = 0.f;

  for (int e = 0; e < E_N; ++e) {
    const float* Wbase = We + (size_t)e * H_N * D_IN;
    float acc[2][8][4];
#pragma unroll
    for (int a = 0; a < 2; ++a)
#pragma unroll
      for (int b = 0; b < 8; ++b)
#pragma unroll
        for (int k = 0; k < 4; ++k) acc[a][b][k] = 0.f;

#pragma unroll
    for (int it = 0; it < 2; ++it) {
      int i = tid + it * NT, r = i >> 3, j4 = i & 7;
      cp16(sb + FB_A0 + r * 144 + j4 * 16, Abase + (size_t)r * D_IN + j4 * 4);
    }
#pragma unroll
    for (int it = 0; it < 4; ++it) {
      int i = tid + it * NT, r = i >> 3, j4 = i & 7;
      cp16(sb + FB_W0 + r * 144 + j4 * 16, Wbase + (size_t)r * D_IN + j4 * 4);
    }
    cp_commit();

    for (int c = 0; c < NCH; ++c) {
      if (c + 1 < NCH) {
        const uint32_t ab = ((c + 1) & 1) ? (sb + FB_A1) : (sb + FB_A0);
        const uint32_t wb = ((c + 1) & 1) ? (sb + FB_W1) : (sb + FB_W0);
        const int k0 = (c + 1) * KC;
#pragma unroll
        for (int it = 0; it < 2; ++it) {
          int i = tid + it * NT, r = i >> 3, j4 = i & 7;
          cp16(ab + r * 144 + j4 * 16, Abase + (size_t)r * D_IN + k0 + j4 * 4);
        }
#pragma unroll
        for (int it = 0; it < 4; ++it) {
          int i = tid + it * NT, r = i >> 3, j4 = i & 7;
          cp16(wb + r * 144 + j4 * 16, Wbase + (size_t)r * D_IN + k0 + j4 * 4);
        }
        cp_commit();
        cp_wait<1>();
      } else {
        cp_wait<0>();
      }
      __syncthreads();

      const float* Asf = (const float*)(smem + ((c & 1) ? FB_A1 : FB_A0));
      const float* Wsf = (const float*)(smem + ((c & 1) ? FB_W1 : FB_W0));

      if (e == 0) {
#pragma unroll
        for (int j4 = 0; j4 < 8; ++j4) {
          float4 x = *(const float4*)(Asf + grow * 36 + j4 * 4);
#pragma unroll
          for (int q = 0; q < 2; ++q) {
            const float* wrow = (const float*)(smem + FB_WG) +
                                (gelo + q) * D_IN + c * KC + j4 * 4;
            gacc[q] += x.x * wrow[0] + x.y * wrow[1] + x.z * wrow[2] + x.w * wrow[3];
          }
        }
      }

#pragma unroll
      for (int ks = 0; ks < 4; ++ks) {
        const int kk = ks * 8;
        uint32_t a[2][4];
#pragma unroll
        for (int mt = 0; mt < 2; ++mt) {
          const int r = wm * 32 + mt * 16;
          a[mt][0] = f2tf(Asf[(r + g) * 36 + kk + t4]);
          a[mt][1] = f2tf(Asf[(r + g + 8) * 36 + kk + t4]);
          a[mt][2] = f2tf(Asf[(r + g) * 36 + kk + t4 + 4]);
          a[mt][3] = f2tf(Asf[(r + g + 8) * 36 + kk + t4 + 4]);
        }
#pragma unroll
        for (int nt = 0; nt < 8; ++nt) {
          const int n = wn * 64 + nt * 8 + g;
          const uint32_t b0 = f2tf(Wsf[n * 36 + kk + t4]);
          const uint32_t b1 = f2tf(Wsf[n * 36 + kk + t4 + 4]);
#pragma unroll
          for (int mt = 0; mt < 2; ++mt)
            mma_s(acc[mt][nt][0], acc[mt][nt][1], acc[mt][nt][2], acc[mt][nt][3],
                  a[mt][0], a[mt][1], a[mt][2], a[mt][3], b0, b1);
        }
      }
      __syncthreads();
    }

    if (e == 0) {
#pragma unroll
      for (int q = 0; q < 2; ++q)
        gsm[grow * 8 + gelo + q] = gacc[q] + bg[gelo + q];
      __syncthreads();
      if (tid < BM) {
        float l[E_N], mx = -1e30f;
#pragma unroll
        for (int i = 0; i < E_N; ++i) { l[i] = gsm[tid * 8 + i]; mx = fmaxf(mx, l[i]); }
        float s = 0.f;
#pragma unroll
        for (int i = 0; i < E_N; ++i) { l[i] = __expf(l[i] - mx); s += l[i]; }
        float inv = 1.0f / s;
#pragma unroll
        for (int i = 0; i < E_N; ++i) gsm[tid * 8 + i] = l[i] * inv;
      }
      __syncthreads();
    }

    const float* be_e = be + (size_t)e * H_N;
#pragma unroll
    for (int mt = 0; mt < 2; ++mt) {
      const int ra = wm * 32 + mt * 16 + g;
      const int rb = ra + 8;
      const float gva = gsm[ra * 8 + e];
      const float gvb = gsm[rb * 8 + e];
#pragma unroll
      for (int nt = 0; nt < 8; ++nt) {
        const int col = wn * 64 + nt * 8 + 2 * t4;
        const float b0 = be_e[col], b1 = be_e[col + 1];
        uint2 pa, pb;
        pa.x = f2tf(fmaxf(acc[mt][nt][0] + b0, 0.f) * gva);
        pa.y = f2tf(fmaxf(acc[mt][nt][1] + b1, 0.f) * gva);
        pb.x = f2tf(fmaxf(acc[mt][nt][2] + b0, 0.f) * gvb);
        pb.y = f2tf(fmaxf(acc[mt][nt][3] + b1, 0.f) * gvb);
        *(uint2*)(Yw + ra * 260 + col) = pa;
        *(uint2*)(Yw + rb * 260 + col) = pb;
      }
    }
    __syncthreads();

#pragma unroll 4
    for (int ks = 0; ks < 32; ++ks) {
      const int kk = ks * 8;
      uint32_t ta[2][4];
#pragma unroll
      for (int mt = 0; mt < 2; ++mt) {
        const int r = wm * 32 + mt * 16;
        ta[mt][0] = Ysu[(r + g) * 260 + kk + t4];
        ta[mt][1] = Ysu[(r + g + 8) * 260 + kk + t4];
        ta[mt][2] = Ysu[(r + g) * 260 + kk + t4 + 4];
        ta[mt][3] = Ysu[(r + g + 8) * 260 + kk + t4 + 4];
      }
#pragma unroll
      for (int nt = 0; nt < 2; ++nt) {
        const int n = wn * 16 + nt * 8 + g;
        const uint32_t b0 = WTu[n * 260 + kk + t4];
        const uint32_t b1 = WTu[n * 260 + kk + t4 + 4];
#pragma unroll
        for (int mt = 0; mt < 2; ++mt)
          mma_s(z[mt][nt][0], z[mt][nt][1], z[mt][nt][2], z[mt][nt][3],
                ta[mt][0], ta[mt][1], ta[mt][2], ta[mt][3], b0, b1);
      }
    }
    __syncthreads();
  }

#pragma unroll
  for (int mt = 0; mt < 2; ++mt) {
    const int ra = wm * 32 + mt * 16 + g;
    const int rb = ra + 8;
#pragma unroll
    for (int nt = 0; nt < 2; ++nt) {
      const int col = wn * 16 + nt * 8 + 2 * t4;
      const float b0 = bt[col], b1 = bt[col + 1];
      float2 va, vb;
      va.x = sigmoidf_(z[mt][nt][0] + b0);
      va.y = sigmoidf_(z[mt][nt][1] + b1);
      vb.x = sigmoidf_(z[mt][nt][2] + b0);
      vb.y = sigmoidf_(z[mt][nt][3] + b1);
      *(float2*)(out + (size_t)(row0 + ra) * T_N + col) = va;
      *(float2*)(out + (size_t)(row0 + rb) * T_N + col) = vb;
    }
  }
#endif
}

extern "C" void kernel_launch(void* const* d_in, const int* in_sizes, int n_in,
                              void* d_out, int out_size) {
  const float* xv = (const float*)d_in[0];
  const float* We = (const float*)d_in[1];
  const float* be = (const float*)d_in[2];
  const float* Wg = (const float*)d_in[3];
  const float* bg = (const float*)d_in[4];
  const float* Wt = (const float*)d_in[5];
  const float* bt = (const float*)d_in[6];
  float* out = (float*)d_out;

  const int B = in_sizes[0] / D_IN;  // 16384
  const int grid = B / BM;           // 128

  static int attr_set = 0;
  if (!attr_set) {
    cudaFuncSetAttribute(mmoe_fused_kernel,
                         cudaFuncAttributeMaxDynamicSharedMemorySize, SMEM_SZ);
    cudaFuncSetAttribute(mmoe_fused_kernel,
                         cudaFuncAttributeNonPortableClusterSizeAllowed, 1);
    attr_set = 1;
  }

  const int n_xv4 = (B * D_IN) / 4;
  const int total4 = n_xv4 + (E_N * H_N * D_IN) / 4;
  preround_kernel<<<(total4 + 255) / 256, 256>>>(xv, We, n_xv4);

  cudaLaunchConfig_t cfg = {};
  cfg.gridDim = {(unsigned)grid, 1, 1};
  cfg.blockDim = {NT, 1, 1};
  cfg.dynamicSmemBytes = SMEM_SZ;
  cudaLaunchAttribute attrs[1];
  attrs[0].id = cudaLaunchAttributeClusterDimension;
  attrs[0].val.clusterDim = {2, 1, 1};
  cfg.attrs = attrs;
  cfg.numAttrs = 1;
  cudaLaunchKernelEx(&cfg, mmoe_fused_kernel, xv, We, be, Wg, bg, Wt, bt, out);
}